// round 3
// baseline (speedup 1.0000x reference)
#include <cuda_runtime.h>
#include <cstdint>

#define BB 8
#define TT 128
#define DD 512
#define OO 512
#define CPG 8              // CTAs per cluster (one cluster per batch)
#define OSL (OO/CPG)       // 64  output-col slice per CTA
#define TSL (TT/CPG)       // 16  timestep slice per CTA (scores phase)
#define NTH 256
#define FULLMASK 0xffffffffu

// ---------------- device scratch (no allocations allowed) ----------------
__device__ float g_UaH[BB*TT*OO];   // inputs@Ua + Ba
__device__ float g_IC [BB*TT*OO];   // inputs@Co
__device__ float g_XUo[BB*TT*OO];   // inputs@Uo
__device__ float g_embWo[OO];       // emb@Wo

// ---------------- helpers ----------------
__device__ __forceinline__ float wredsum(float v) {
    #pragma unroll
    for (int s = 16; s; s >>= 1) v += __shfl_xor_sync(FULLMASK, v, s);
    return v;
}
__device__ __forceinline__ float wredmax(float v) {
    #pragma unroll
    for (int s = 16; s; s >>= 1) v = fmaxf(v, __shfl_xor_sync(FULLMASK, v, s));
    return v;
}
__device__ __forceinline__ float tanhapx(float x) {
    float y;
    asm("tanh.approx.f32 %0, %1;" : "=f"(y) : "f"(x));
    return y;
}
__device__ __forceinline__ uint32_t smem_u32(const void* p) {
    uint32_t a;
    asm("{ .reg .u64 t; cvta.to.shared.u64 t, %1; cvt.u32.u64 %0, t; }"
        : "=r"(a) : "l"(p));
    return a;
}
__device__ __forceinline__ void dsm_st(uint32_t laddr, uint32_t rank, float v) {
    uint32_t r;
    asm volatile("mapa.shared::cluster.u32 %0, %1, %2;" : "=r"(r) : "r"(laddr), "r"(rank));
    asm volatile("st.shared::cluster.f32 [%0], %1;" :: "r"(r), "f"(v) : "memory");
}
#define CLUSTER_SYNC() do { \
    asm volatile("barrier.cluster.arrive.aligned;" ::: "memory"); \
    asm volatile("barrier.cluster.wait.aligned;"   ::: "memory"); \
} while (0)

// =======================================================================
// GEMM: C_z = A[1024x512] @ B_z[512x512], z=0:Ua(+Ba), 1:Co, 2:Uo
// 64x64 tile, BK=16, 256 threads, 4x4 per thread.
// =======================================================================
__global__ __launch_bounds__(256) void gemm3_kernel(
    const float* __restrict__ A,
    const float* __restrict__ Ua,
    const float* __restrict__ Co,
    const float* __restrict__ Uo,
    const float* __restrict__ Ba)
{
    __shared__ float As[16][64];   // k-major
    __shared__ float Bs[16][64];

    const int m0 = blockIdx.x * 64;
    const int n0 = blockIdx.y * 64;
    const int z  = blockIdx.z;
    const float* __restrict__ Bm = (z == 0) ? Ua : ((z == 1) ? Co : Uo);
    float* Cout = (z == 0) ? g_UaH : ((z == 1) ? g_IC : g_XUo);

    const int tid  = threadIdx.x;
    const int tx   = tid & 15;
    const int ty   = tid >> 4;
    const int la_m = tid >> 2;
    const int la_k = (tid & 3) << 2;
    const int lb_k = tid >> 4;
    const int lb_n = (tid & 15) << 2;

    float acc[4][4];
    #pragma unroll
    for (int i = 0; i < 4; i++)
        #pragma unroll
        for (int j = 0; j < 4; j++) acc[i][j] = 0.f;

    for (int k0 = 0; k0 < DD; k0 += 16) {
        float4 av = *(const float4*)&A [(m0 + la_m) * DD + k0 + la_k];
        float4 bv = *(const float4*)&Bm[(k0 + lb_k) * OO + n0 + lb_n];
        __syncthreads();
        As[la_k + 0][la_m] = av.x;
        As[la_k + 1][la_m] = av.y;
        As[la_k + 2][la_m] = av.z;
        As[la_k + 3][la_m] = av.w;
        *(float4*)&Bs[lb_k][lb_n] = bv;
        __syncthreads();
        #pragma unroll
        for (int kk = 0; kk < 16; kk++) {
            float4 a = *(const float4*)&As[kk][ty << 2];
            float4 b = *(const float4*)&Bs[kk][tx << 2];
            acc[0][0] += a.x * b.x; acc[0][1] += a.x * b.y; acc[0][2] += a.x * b.z; acc[0][3] += a.x * b.w;
            acc[1][0] += a.y * b.x; acc[1][1] += a.y * b.y; acc[1][2] += a.y * b.z; acc[1][3] += a.y * b.w;
            acc[2][0] += a.z * b.x; acc[2][1] += a.z * b.y; acc[2][2] += a.z * b.z; acc[2][3] += a.z * b.w;
            acc[3][0] += a.w * b.x; acc[3][1] += a.w * b.y; acc[3][2] += a.w * b.z; acc[3][3] += a.w * b.w;
        }
    }
    #pragma unroll
    for (int i = 0; i < 4; i++) {
        int r = m0 + (ty << 2) + i;
        #pragma unroll
        for (int j = 0; j < 4; j++) {
            int c = n0 + (tx << 2) + j;
            float v = acc[i][j];
            if (z == 0) v += Ba[c];
            Cout[r * OO + c] = v;
        }
    }
}

// =======================================================================
// embWo[i] = sum_j emb[i][j] * Wo[j]   (one warp per row)
// =======================================================================
__global__ __launch_bounds__(256) void embwo_kernel(
    const float* __restrict__ emb, const float* __restrict__ Wo)
{
    const int row  = (blockIdx.x << 3) + (threadIdx.x >> 5);
    const int lane = threadIdx.x & 31;
    const float* rp = emb + row * OO;
    float acc = 0.f;
    #pragma unroll 4
    for (int j = lane; j < OO; j += 32) acc += rp[j] * Wo[j];
    acc = wredsum(acc);
    if (lane == 0) g_embWo[row] = acc;
}

// =======================================================================
// Persistent clustered scan. Cluster of 8 CTAs = one batch.
// =======================================================================
// shared memory layout (float offsets)
#define UAH_OFF   0                        // [16][512]  = 8192
#define IC_OFF    (UAH_OFF + TSL*OO)       // [128][64]  = 8192
#define PRED_OFF  (IC_OFF + TT*OSL)        // [512]
#define SSIG_OFF  (PRED_OFF + OO)          // [512]
#define WAS_OFF   (SSIG_OFF + OO)          // [512]
#define SC_OFF    (WAS_OFF + OO)           // [128]
#define WBUF_OFF  (SC_OFF + TT)            // [128]
#define RED_OFF   (WBUF_OFF + TT)          // [32]
#define PART_OFF  (RED_OFF + 32)           // [256]
#define SMEM_FLOATS (PART_OFF + 256)
#define SMEM_BYTES  (SMEM_FLOATS * 4)      // 73856 B

__global__ __launch_bounds__(NTH, 1) __cluster_dims__(CPG, 1, 1)
void scan_kernel(const float* __restrict__ Wa,
                 const float* __restrict__ Va,
                 const float* __restrict__ Bo,
                 float* __restrict__ out)
{
    extern __shared__ float sm[];
    float* UaH_s  = sm + UAH_OFF;
    float* IC_s   = sm + IC_OFF;
    float* pred_s = sm + PRED_OFF;
    float* s_sig  = sm + SSIG_OFF;
    float* WaS_s  = sm + WAS_OFF;
    float* sc_s   = sm + SC_OFF;
    float* wbuf   = sm + WBUF_OFF;
    float* red    = sm + RED_OFF;
    float* part   = sm + PART_OFF;

    const uint32_t sbase     = smem_u32(sm);
    const uint32_t was_addr  = sbase + WAS_OFF  * 4;
    const uint32_t sc_addr   = sbase + SC_OFF   * 4;
    const uint32_t pred_addr = sbase + PRED_OFF * 4;

    const int tid  = threadIdx.x;
    const int lane = tid & 31;
    const int wid  = tid >> 5;
    const int b    = blockIdx.x >> 3;     // batch
    const int crk  = blockIdx.x & 7;      // cluster rank
    const int o_base = crk * OSL;
    const int t_base = crk * TSL;
    const int oc = tid & 63;
    const int kc = tid >> 6;              // 0..3
    const int tc = tid >> 6;              // same split for P3

    // ---------------- prologue ----------------
    {
        const float4* src = (const float4*)(g_UaH + (size_t)(b * TT + t_base) * OO);
        float4* dst = (float4*)UaH_s;
        for (int i = tid; i < (TSL * OO) / 4; i += NTH) dst[i] = src[i];
    }
    {
        float4* dst = (float4*)IC_s;
        for (int i = tid; i < (TT * OSL) / 4; i += NTH) {
            int row = i >> 4, c4 = i & 15;
            dst[i] = *(const float4*)(g_IC + (size_t)(b * TT + row) * OO + o_base + (c4 << 2));
        }
    }
    for (int i = tid; i < OO; i += NTH) pred_s[i] = 0.f;

    float wreg[128];      // Wa[kc*128 + i][o_base + oc]
    #pragma unroll
    for (int i = 0; i < 128; i++)
        wreg[i] = Wa[(kc * 128 + i) * OO + o_base + oc];

    float va_r[16];
    #pragma unroll
    for (int j = 0; j < 16; j++) va_r[j] = Va[(j << 5) + lane];

    const float ew0  = g_embWo[tid];
    const float ew1  = g_embWo[tid + 256];
    const float bo_r = (tid < OSL) ? Bo[o_base + tid] : 0.f;
    __syncthreads();

    // ---------------- scan over T steps ----------------
    for (int t = 0; t < TT; t++) {
        // prefetch XUo[b, (t-1) mod T, o-slice]
        float xo = 0.f;
        if (tid < OSL)
            xo = __ldg(&g_XUo[(size_t)(b * TT + ((t + TT - 1) & (TT - 1))) * OO + o_base + tid]);

        // ================= P1: sigmoid / WoY / WaS =================
        float pv0 = pred_s[tid];
        float pv1 = pred_s[tid + 256];

        float lm = wredmax(fmaxf(pv0, pv1));
        if (lane == 0) red[wid] = lm;
        __syncthreads();                         // (A)
        float mx = red[0];
        #pragma unroll
        for (int i = 1; i < 8; i++) mx = fmaxf(mx, red[i]);

        float e0 = __expf(pv0 - mx), e1 = __expf(pv1 - mx);
        float ps = wredsum(e0 + e1);
        float pd = wredsum(e0 * ew0 + e1 * ew1);
        if (lane == 0) { red[8 + wid] = ps; red[16 + wid] = pd; }
        s_sig[tid]       = __fdividef(1.f, 1.f + __expf(-pv0));
        s_sig[tid + 256] = __fdividef(1.f, 1.f + __expf(-pv1));
        __syncthreads();                         // (B) red + s_sig ready

        float S = 0.f, P = 0.f;
        #pragma unroll
        for (int i = 0; i < 8; i++) { S += red[8 + i]; P += red[16 + i]; }
        const float woy = __fdividef(P, S);

        // WaS partials: thread (oc, kc) covers k in [kc*128, kc*128+128)
        {
            const float4* sp4 = (const float4*)(s_sig + kc * 128);
            float acc = 0.f;
            #pragma unroll
            for (int i = 0; i < 32; i++) {
                float4 s4 = sp4[i];
                acc += s4.x * wreg[4*i]   + s4.y * wreg[4*i+1]
                     + s4.z * wreg[4*i+2] + s4.w * wreg[4*i+3];
            }
            part[(kc << 6) + oc] = acc;
        }
        __syncthreads();                         // (C)
        if (tid < OSL) {
            float w = part[tid] + part[64 + tid] + part[128 + tid] + part[192 + tid];
            uint32_t a = was_addr + ((uint32_t)(o_base + tid) << 2);
            #pragma unroll
            for (int r = 0; r < CPG; r++) dsm_st(a, r, w);
        }
        CLUSTER_SYNC();                          // sync1: WaS_s[512] complete everywhere

        // ================= P2: scores over this CTA's t-slice =================
        #pragma unroll
        for (int h = 0; h < 2; h++) {
            const int tloc = (wid << 1) + h;     // 0..15
            const float* urow = UaH_s + tloc * OO;
            float acc = 0.f;
            #pragma unroll
            for (int j = 0; j < 16; j++) {
                int o = (j << 5) + lane;
                acc += tanhapx(urow[o] + WaS_s[o]) * va_r[j];
            }
            acc = wredsum(acc);
            if (lane == 0) {
                uint32_t a = sc_addr + ((uint32_t)(t_base + tloc) << 2);
                #pragma unroll
                for (int r = 0; r < CPG; r++) dsm_st(a, r, acc);
            }
        }
        CLUSTER_SYNC();                          // sync2: sc_s[128] complete everywhere

        // ================= P3: softmax over T + pred =================
        float v = 0.f;
        if (tid < TT) {
            v = sc_s[tid];
            float m = wredmax(v);
            if (lane == 0) red[wid] = m;         // warps 0..3
        }
        __syncthreads();                         // (a)
        float smax = fmaxf(fmaxf(red[0], red[1]), fmaxf(red[2], red[3]));
        if (tid < TT) {
            float e = __expf(v - smax);
            wbuf[tid] = e;
            float s = wredsum(e);
            if (lane == 0) red[8 + wid] = s;
        }
        __syncthreads();                         // (b)
        float esum = (red[8] + red[9]) + (red[10] + red[11]);

        // weighted IC sum: thread (oc, tc) covers t' in [tc*32, tc*32+32)
        {
            float acc = 0.f;
            const int base = tc << 5;
            #pragma unroll
            for (int i = 0; i < 32; i++)
                acc += wbuf[base + i] * IC_s[((base + i) << 6) + oc];
            part[(tc << 6) + oc] = acc;
        }
        __syncthreads();                         // (c)
        if (tid < OSL) {
            float ctx  = part[tid] + part[64 + tid] + part[128 + tid] + part[192 + tid];
            float pred = woy + xo + __fdividef(ctx, esum) + bo_r;
            out[(size_t)(b * TT + t) * OO + o_base + tid] = pred;
            uint32_t a = pred_addr + ((uint32_t)(o_base + tid) << 2);
            #pragma unroll
            for (int r = 0; r < CPG; r++) dsm_st(a, r, pred);
        }
        CLUSTER_SYNC();                          // sync3: pred_s[512] complete everywhere
    }
}

// =======================================================================
// launch
// =======================================================================
extern "C" void kernel_launch(void* const* d_in, const int* in_sizes, int n_in,
                              void* d_out, int out_size)
{
    const float* inputs = (const float*)d_in[0];
    const float* Wa     = (const float*)d_in[1];
    const float* Ua     = (const float*)d_in[2];
    const float* Va     = (const float*)d_in[3];
    const float* Ba     = (const float*)d_in[4];
    const float* Wo     = (const float*)d_in[5];
    const float* Uo     = (const float*)d_in[6];
    const float* Co     = (const float*)d_in[7];
    const float* Bo     = (const float*)d_in[8];
    const float* emb    = (const float*)d_in[9];
    float* out = (float*)d_out;

    dim3 g(16, 8, 3);
    gemm3_kernel<<<g, 256>>>(inputs, Ua, Co, Uo, Ba);
    embwo_kernel<<<64, 256>>>(emb, Wo);

    cudaFuncSetAttribute(scan_kernel,
                         cudaFuncAttributeMaxDynamicSharedMemorySize, SMEM_BYTES);
    scan_kernel<<<BB * CPG, NTH, SMEM_BYTES>>>(Wa, Va, Bo, out);
}

// round 4
// speedup vs baseline: 1.3099x; 1.3099x over previous
#include <cuda_runtime.h>
#include <cstdint>

#define BB 8
#define TT 128
#define DD 512
#define OO 512
#define CPG 8              // CTAs per cluster (one cluster per batch)
#define OSL (OO/CPG)       // 64  output-col slice per CTA
#define NTH 256
#define FULLMASK 0xffffffffu

// ---------------- device scratch (no allocations allowed) ----------------
__device__ float g_UaH[BB*TT*OO];   // inputs@Ua + Ba
__device__ float g_IC [BB*TT*OO];   // inputs@Co
__device__ float g_XUo[BB*TT*OO];   // inputs@Uo
__device__ float g_embWo[OO];       // emb@Wo

// ---------------- helpers ----------------
__device__ __forceinline__ float wredsum(float v) {
    #pragma unroll
    for (int s = 16; s; s >>= 1) v += __shfl_xor_sync(FULLMASK, v, s);
    return v;
}
__device__ __forceinline__ float tanhapx(float x) {
    float y;
    asm("tanh.approx.f32 %0, %1;" : "=f"(y) : "f"(x));
    return y;
}
__device__ __forceinline__ uint32_t smem_u32(const void* p) {
    uint32_t a;
    asm("{ .reg .u64 t; cvta.to.shared.u64 t, %1; cvt.u32.u64 %0, t; }"
        : "=r"(a) : "l"(p));
    return a;
}
__device__ __forceinline__ uint32_t dsm_map(uint32_t laddr, uint32_t rank) {
    uint32_t r;
    asm("mapa.shared::cluster.u32 %0, %1, %2;" : "=r"(r) : "r"(laddr), "r"(rank));
    return r;
}
__device__ __forceinline__ void dsm_st(uint32_t raddr, float v) {
    asm volatile("st.shared::cluster.f32 [%0], %1;" :: "r"(raddr), "f"(v) : "memory");
}
#define CLUSTER_SYNC() do { \
    asm volatile("barrier.cluster.arrive.aligned;" ::: "memory"); \
    asm volatile("barrier.cluster.wait.aligned;"   ::: "memory"); \
} while (0)

// =======================================================================
// GEMM: C_z = A[1024x512] @ B_z[512x512], z=0:Ua(+Ba), 1:Co, 2:Uo
// 64x64 tile, BK=16, 256 threads, 4x4 per thread.  (measured 60us)
// =======================================================================
__global__ __launch_bounds__(256) void gemm3_kernel(
    const float* __restrict__ A,
    const float* __restrict__ Ua,
    const float* __restrict__ Co,
    const float* __restrict__ Uo,
    const float* __restrict__ Ba)
{
    __shared__ float As[16][64];   // k-major
    __shared__ float Bs[16][64];

    const int m0 = blockIdx.x * 64;
    const int n0 = blockIdx.y * 64;
    const int z  = blockIdx.z;
    const float* __restrict__ Bm = (z == 0) ? Ua : ((z == 1) ? Co : Uo);
    float* Cout = (z == 0) ? g_UaH : ((z == 1) ? g_IC : g_XUo);

    const int tid  = threadIdx.x;
    const int tx   = tid & 15;
    const int ty   = tid >> 4;
    const int la_m = tid >> 2;
    const int la_k = (tid & 3) << 2;
    const int lb_k = tid >> 4;
    const int lb_n = (tid & 15) << 2;

    float acc[4][4];
    #pragma unroll
    for (int i = 0; i < 4; i++)
        #pragma unroll
        for (int j = 0; j < 4; j++) acc[i][j] = 0.f;

    for (int k0 = 0; k0 < DD; k0 += 16) {
        float4 av = *(const float4*)&A [(m0 + la_m) * DD + k0 + la_k];
        float4 bv = *(const float4*)&Bm[(k0 + lb_k) * OO + n0 + lb_n];
        __syncthreads();
        As[la_k + 0][la_m] = av.x;
        As[la_k + 1][la_m] = av.y;
        As[la_k + 2][la_m] = av.z;
        As[la_k + 3][la_m] = av.w;
        *(float4*)&Bs[lb_k][lb_n] = bv;
        __syncthreads();
        #pragma unroll
        for (int kk = 0; kk < 16; kk++) {
            float4 a = *(const float4*)&As[kk][ty << 2];
            float4 b = *(const float4*)&Bs[kk][tx << 2];
            acc[0][0] += a.x * b.x; acc[0][1] += a.x * b.y; acc[0][2] += a.x * b.z; acc[0][3] += a.x * b.w;
            acc[1][0] += a.y * b.x; acc[1][1] += a.y * b.y; acc[1][2] += a.y * b.z; acc[1][3] += a.y * b.w;
            acc[2][0] += a.z * b.x; acc[2][1] += a.z * b.y; acc[2][2] += a.z * b.z; acc[2][3] += a.z * b.w;
            acc[3][0] += a.w * b.x; acc[3][1] += a.w * b.y; acc[3][2] += a.w * b.z; acc[3][3] += a.w * b.w;
        }
    }
    #pragma unroll
    for (int i = 0; i < 4; i++) {
        int r = m0 + (ty << 2) + i;
        #pragma unroll
        for (int j = 0; j < 4; j++) {
            int c = n0 + (tx << 2) + j;
            float v = acc[i][j];
            if (z == 0) v += Ba[c];
            Cout[r * OO + c] = v;
        }
    }
}

// =======================================================================
// embWo[i] = sum_j emb[i][j] * Wo[j]   (one warp per row)
// =======================================================================
__global__ __launch_bounds__(256) void embwo_kernel(
    const float* __restrict__ emb, const float* __restrict__ Wo)
{
    const int row  = (blockIdx.x << 3) + (threadIdx.x >> 5);
    const int lane = threadIdx.x & 31;
    const float* rp = emb + row * OO;
    float acc = 0.f;
    #pragma unroll 4
    for (int j = lane; j < OO; j += 32) acc += rp[j] * Wo[j];
    acc = wredsum(acc);
    if (lane == 0) g_embWo[row] = acc;
}

// =======================================================================
// Persistent clustered scan, o-split everywhere. Cluster of 8 CTAs = one batch.
// Two cluster syncs per step.
// =======================================================================
#define UAH_PITCH 65
// shared memory layout (float offsets)
#define UAH_OFF   0                            // [128 t][65]  = 8320
#define IC_OFF    (UAH_OFF + TT*UAH_PITCH)     // [128 t][64 o]= 8192
#define PRED_OFF  (IC_OFF + TT*OSL)            // [512] full pred (bcast target)
#define SIG_OFF   (PRED_OFF + OO)              // [512] sigmoid(pred)
#define SPART_OFF (SIG_OFF + OO)               // [8 rank][128 t] score partials (bcast target)
#define WBUF_OFF  (SPART_OFF + CPG*TT)         // [128] exp weights
#define WAS_OFF   (WBUF_OFF + TT)              // [64] own WaS slice
#define VA_OFF    (WAS_OFF + OSL)              // [64] Va slice
#define RED_OFF   (VA_OFF + OSL)               // [32]
#define PART_OFF  (RED_OFF + 32)               // [256]
#define SMEM_FLOATS (PART_OFF + 256)
#define SMEM_BYTES  (SMEM_FLOATS * 4)

__global__ __launch_bounds__(NTH, 1) __cluster_dims__(CPG, 1, 1)
void scan_kernel(const float* __restrict__ Wa,
                 const float* __restrict__ Va,
                 const float* __restrict__ Bo,
                 float* __restrict__ out)
{
    extern __shared__ float sm[];
    float* UaH_s  = sm + UAH_OFF;
    float* IC_s   = sm + IC_OFF;
    float* pred_s = sm + PRED_OFF;
    float* sig_s  = sm + SIG_OFF;
    float* spart  = sm + SPART_OFF;
    float* wbuf   = sm + WBUF_OFF;
    float* WaS_s  = sm + WAS_OFF;
    float* va_s   = sm + VA_OFF;
    float* red    = sm + RED_OFF;
    float* part   = sm + PART_OFF;

    const uint32_t sbase = smem_u32(sm);

    const int tid  = threadIdx.x;
    const int lane = tid & 31;
    const int wid  = tid >> 5;
    const int b    = blockIdx.x >> 3;     // batch
    const int crk  = blockIdx.x & 7;      // cluster rank
    const int o_base = crk * OSL;
    const int oc = tid & 63;              // o within slice
    const int kc = tid >> 6;              // k quarter (P1) / t quarter (P3)
    const int ts = tid & 127;             // timestep (P2)
    const int hf = tid >> 7;              // o half (P2)

    // ---------------- prologue ----------------
    // UaH slice [128 t][64 o], pitch 65 (conflict-free P2 reads)
    for (int i = tid; i < TT * OSL; i += NTH) {
        int tt = i >> 6, o = i & 63;
        UaH_s[tt * UAH_PITCH + o] = g_UaH[(size_t)(b * TT + tt) * OO + o_base + o];
    }
    // IC slice [128 t][64 o]
    for (int i = tid; i < TT * OSL; i += NTH) {
        int tt = i >> 6, o = i & 63;
        IC_s[(tt << 6) + o] = g_IC[(size_t)(b * TT + tt) * OO + o_base + o];
    }
    for (int i = tid; i < OO; i += NTH) pred_s[i] = 0.f;
    if (tid < OSL) va_s[tid] = Va[o_base + tid];

    // Wa slice in registers: thread (oc, kc) holds Wa[kc*128+i][o_base+oc]
    float wreg[128];
    #pragma unroll
    for (int i = 0; i < 128; i++)
        wreg[i] = Wa[(kc * 128 + i) * OO + o_base + oc];

    const float ew0  = g_embWo[tid];
    const float ew1  = g_embWo[tid + 256];
    const float bo_r = (tid < OSL) ? Bo[o_base + tid] : 0.f;

    // precomputed remote addresses (loop-invariant)
    uint32_t sc_raddr[CPG];      // spart[crk][ts] in every CTA   (tid < 128)
    uint32_t pr_raddr[CPG];      // pred_s[o_base + tid] in every CTA (tid < 64)
    {
        uint32_t a1 = sbase + (uint32_t)(SPART_OFF + crk * TT + ts) * 4u;
        uint32_t a2 = sbase + (uint32_t)(PRED_OFF + o_base + (tid & 63)) * 4u;
        #pragma unroll
        for (int r = 0; r < CPG; r++) {
            sc_raddr[r] = dsm_map(a1, r);
            pr_raddr[r] = dsm_map(a2, r);
        }
    }
    __syncthreads();

    // ---------------- scan over T steps ----------------
    for (int t = 0; t < TT; t++) {
        // prefetch XUo[b, (t-1) mod T, own o-slice]
        float xo = 0.f;
        if (tid < OSL)
            xo = __ldg(&g_XUo[(size_t)(b * TT + ((t + TT - 1) & (TT - 1))) * OO + o_base + tid]);

        // ============ P1': woy scalars + sigmoid + own-slice WaS ============
        float pv0 = pred_s[tid];
        float pv1 = pred_s[tid + 256];
        float e0 = __expf(pv0), e1 = __expf(pv1);         // |pred| small: no max-sub needed
        sig_s[tid]       = __fdividef(1.f, 1.f + __expf(-pv0));
        sig_s[tid + 256] = __fdividef(1.f, 1.f + __expf(-pv1));
        float ps = wredsum(e0 + e1);
        float pd = wredsum(e0 * ew0 + e1 * ew1);
        if (lane == 0) { red[wid] = ps; red[8 + wid] = pd; }
        __syncthreads();                                   // (1) red + sig_s ready

        float S = 0.f, P = 0.f;
        #pragma unroll
        for (int i = 0; i < 8; i++) { S += red[i]; P += red[8 + i]; }
        const float woy = __fdividef(P, S);

        // WaS partial: thread (oc,kc) covers k in [kc*128, kc*128+128)
        {
            const float4* sp4 = (const float4*)(sig_s + kc * 128);
            float acc = 0.f;
            #pragma unroll
            for (int i = 0; i < 32; i++) {
                float4 s4 = sp4[i];
                acc += s4.x * wreg[4*i]   + s4.y * wreg[4*i+1]
                     + s4.z * wreg[4*i+2] + s4.w * wreg[4*i+3];
            }
            part[tid] = acc;
        }
        __syncthreads();                                   // (2)
        if (tid < OSL)
            WaS_s[tid] = part[tid] + part[64 + tid] + part[128 + tid] + part[192 + tid];
        __syncthreads();                                   // (3) WaS_s ready

        // ============ P2': partial scores for ALL t over own o-half ============
        {
            const float* urow = UaH_s + ts * UAH_PITCH + (hf << 5);
            const float* wp   = WaS_s + (hf << 5);
            const float* vp   = va_s  + (hf << 5);
            float acc = 0.f;
            #pragma unroll
            for (int i = 0; i < 32; i++)
                acc += tanhapx(urow[i] + wp[i]) * vp[i];
            part[(hf << 7) + ts] = acc;
        }
        __syncthreads();                                   // (4)
        if (tid < TT) {
            float s = part[tid] + part[128 + tid];
            #pragma unroll
            for (int r = 0; r < CPG; r++) dsm_st(sc_raddr[r], s);
        }
        CLUSTER_SYNC();                                    // sync#1: spart complete

        // ============ P3': softmax over T + ctx + pred ============
        float esv = 0.f;
        if (tid < TT) {
            float sc = 0.f;
            #pragma unroll
            for (int r = 0; r < CPG; r++) sc += spart[(r << 7) + tid];
            esv = __expf(sc);                              // scores small: no max-sub
            wbuf[tid] = esv;
        }
        float sp = wredsum(esv);                           // warps 4..7 contribute 0
        if (lane == 0) red[16 + wid] = sp;
        __syncthreads();                                   // (5) wbuf + red ready
        const float esum = (red[16] + red[17]) + (red[18] + red[19]);

        // ctx partial: thread (oc,kc) covers t' in [kc*32, kc*32+32)
        {
            float acc = 0.f;
            const int base = kc << 5;
            #pragma unroll
            for (int i = 0; i < 32; i++)
                acc += wbuf[base + i] * IC_s[((base + i) << 6) + oc];
            part[tid] = acc;
        }
        __syncthreads();                                   // (6)
        if (tid < OSL) {
            float ctx  = part[tid] + part[64 + tid] + part[128 + tid] + part[192 + tid];
            float pred = woy + xo + __fdividef(ctx, esum) + bo_r;
            out[(size_t)(b * TT + t) * OO + o_base + tid] = pred;
            #pragma unroll
            for (int r = 0; r < CPG; r++) dsm_st(pr_raddr[r], pred);
        }
        CLUSTER_SYNC();                                    // sync#2: pred_s complete
    }
}

// =======================================================================
// launch
// =======================================================================
extern "C" void kernel_launch(void* const* d_in, const int* in_sizes, int n_in,
                              void* d_out, int out_size)
{
    const float* inputs = (const float*)d_in[0];
    const float* Wa     = (const float*)d_in[1];
    const float* Ua     = (const float*)d_in[2];
    const float* Va     = (const float*)d_in[3];
    const float* Ba     = (const float*)d_in[4];
    const float* Wo     = (const float*)d_in[5];
    const float* Uo     = (const float*)d_in[6];
    const float* Co     = (const float*)d_in[7];
    const float* Bo     = (const float*)d_in[8];
    const float* emb    = (const float*)d_in[9];
    float* out = (float*)d_out;

    dim3 g(16, 8, 3);
    gemm3_kernel<<<g, 256>>>(inputs, Ua, Co, Uo, Ba);
    embwo_kernel<<<64, 256>>>(emb, Wo);

    cudaFuncSetAttribute(scan_kernel,
                         cudaFuncAttributeMaxDynamicSharedMemorySize, SMEM_BYTES);
    scan_kernel<<<BB * CPG, NTH, SMEM_BYTES>>>(Wa, Va, Bo, out);
}